// round 5
// baseline (speedup 1.0000x reference)
#include <cuda_runtime.h>
#include <cuda_bf16.h>
#include <cstdint>

// ---------------------------------------------------------------------------
// Problem constants
// ---------------------------------------------------------------------------
#define N_NODES 50000
#define D_IN    128
#define D_H     128
#define D_OUT   64
#define N_EDGES 800000
#define LN_EPS  1e-5f

// ---------------------------------------------------------------------------
// Scratch (__device__ globals: allocation-free rule)
// ---------------------------------------------------------------------------
__device__ float          g_xw[N_NODES * D_H];          // GEMM out / SpMM in
__device__ __nv_bfloat16  g_h_hi[N_NODES * D_H];        // split hidden state
__device__ __nv_bfloat16  g_h_lo[N_NODES * D_H];
__device__ __nv_bfloat16  g_w_hi[3][128 * 128];         // transposed [n][k] bf16
__device__ __nv_bfloat16  g_w_lo[3][128 * 128];

// ---------------------------------------------------------------------------
// Helpers (sm_80-era PTX only: ldmatrix + mma.sync — no arch-suffix gating)
// ---------------------------------------------------------------------------
__device__ __forceinline__ uint32_t smem_to_u32(const void* p) {
    uint32_t a;
    asm("{ .reg .u64 t; cvta.to.shared.u64 t, %1; cvt.u32.u64 %0, t; }"
        : "=r"(a) : "l"(p));
    return a;
}

__device__ __forceinline__ void ldm_x4(uint32_t& r0, uint32_t& r1,
                                       uint32_t& r2, uint32_t& r3,
                                       uint32_t addr) {
    asm volatile("ldmatrix.sync.aligned.m8n8.x4.shared.b16 {%0,%1,%2,%3}, [%4];"
                 : "=r"(r0), "=r"(r1), "=r"(r2), "=r"(r3) : "r"(addr));
}

__device__ __forceinline__ void mma_bf16(float* d, const uint32_t* a,
                                         uint32_t b0, uint32_t b1) {
    asm volatile(
        "mma.sync.aligned.m16n8k16.row.col.f32.bf16.bf16.f32 "
        "{%0,%1,%2,%3}, {%4,%5,%6,%7}, {%8,%9}, {%0,%1,%2,%3};"
        : "+f"(d[0]), "+f"(d[1]), "+f"(d[2]), "+f"(d[3])
        : "r"(a[0]), "r"(a[1]), "r"(a[2]), "r"(a[3]), "r"(b0), "r"(b1));
}

// ---------------------------------------------------------------------------
// GEMM: C[M, NT] = A[M,128] @ B^T, A = Ahi+Alo, B[n][k] = Bhi+Blo (bf16).
// 3-term split product (hi*hi + hi*lo + lo*hi), fp32 accumulate in HMMA.
// CTA: 256 threads = 8 warps; warp w computes rows [blk*128 + w*16, +16) x NT.
// B staged in smem, rows padded to 136 bf16 (272B = 17x16B -> ldmatrix
// conflict-free). A fragments loaded directly from global (reused across all
// n-tiles in registers).
// ---------------------------------------------------------------------------
template<int NT>
__global__ void __launch_bounds__(256)
gemm_mma(const __nv_bfloat16* __restrict__ Ahi,
         const __nv_bfloat16* __restrict__ Alo,
         const __nv_bfloat16* __restrict__ Bhi,
         const __nv_bfloat16* __restrict__ Blo,
         float* __restrict__ C, int M)
{
    extern __shared__ __nv_bfloat16 sm[];
    __nv_bfloat16* sbh = sm;               // [NT][136]
    __nv_bfloat16* sbl = sm + NT * 136;    // [NT][136]

    // Stage B hi/lo into padded smem (uint4 chunks; rows are 256B in global)
    for (int i = threadIdx.x; i < NT * 16; i += 256) {
        const int n = i >> 4, c = i & 15;
        ((uint4*)(sbh + n * 136))[c] = ((const uint4*)(Bhi + (size_t)n * 128))[c];
        ((uint4*)(sbl + n * 136))[c] = ((const uint4*)(Blo + (size_t)n * 128))[c];
    }
    __syncthreads();

    const int lane = threadIdx.x & 31;
    const int wid  = threadIdx.x >> 5;
    const int g    = lane >> 2;     // octet row
    const int tig  = lane & 3;      // thread-in-group
    const int R    = blockIdx.x * 128 + wid * 16;
    const int row0 = R + g;
    const int row1 = R + g + 8;
    const int cr0  = row0 < M ? row0 : M - 1;   // clamp (values unused if OOB)
    const int cr1  = row1 < M ? row1 : M - 1;

    // ldmatrix per-lane address offset for B matrices:
    // quad q: 0 -> (n+0,k+0), 1 -> (n+0,k+8), 2 -> (n+8,k+0), 3 -> (n+8,k+8)
    const int q  = lane >> 3;
    const int rr = lane & 7;
    const uint32_t lane_off =
        (uint32_t)((((q & 2) ? 8 : 0) + rr) * 272 + ((q & 1) ? 16 : 0));
    const uint32_t sbh_b = smem_to_u32(sbh) + lane_off;
    const uint32_t sbl_b = smem_to_u32(sbl) + lane_off;

    constexpr int NTILE = NT / 8;
    float acc[NTILE][4];
    #pragma unroll
    for (int t = 0; t < NTILE; ++t)
        #pragma unroll
        for (int j = 0; j < 4; ++j) acc[t][j] = 0.f;

    const __nv_bfloat16* Ah0 = Ahi + (size_t)cr0 * 128 + tig * 2;
    const __nv_bfloat16* Ah1 = Ahi + (size_t)cr1 * 128 + tig * 2;
    const __nv_bfloat16* Al0 = Alo + (size_t)cr0 * 128 + tig * 2;
    const __nv_bfloat16* Al1 = Alo + (size_t)cr1 * 128 + tig * 2;

    #pragma unroll
    for (int k0 = 0; k0 < 128; k0 += 16) {
        // A fragments (a0:(g,k), a1:(g+8,k), a2:(g,k+8), a3:(g+8,k+8))
        uint32_t ah[4], al[4];
        ah[0] = *(const uint32_t*)(Ah0 + k0);
        ah[1] = *(const uint32_t*)(Ah1 + k0);
        ah[2] = *(const uint32_t*)(Ah0 + k0 + 8);
        ah[3] = *(const uint32_t*)(Ah1 + k0 + 8);
        al[0] = *(const uint32_t*)(Al0 + k0);
        al[1] = *(const uint32_t*)(Al1 + k0);
        al[2] = *(const uint32_t*)(Al0 + k0 + 8);
        al[3] = *(const uint32_t*)(Al1 + k0 + 8);

        #pragma unroll
        for (int nt2 = 0; nt2 < NT / 16; ++nt2) {
            const uint32_t off = (uint32_t)(nt2 * 16 * 272 + k0 * 2);
            uint32_t bh0, bh1, bh2, bh3, bl0, bl1, bl2, bl3;
            ldm_x4(bh0, bh1, bh2, bh3, sbh_b + off);
            ldm_x4(bl0, bl1, bl2, bl3, sbl_b + off);
            mma_bf16(acc[2 * nt2],     ah, bh0, bh1);
            mma_bf16(acc[2 * nt2 + 1], ah, bh2, bh3);
            mma_bf16(acc[2 * nt2],     ah, bl0, bl1);
            mma_bf16(acc[2 * nt2 + 1], ah, bl2, bl3);
            mma_bf16(acc[2 * nt2],     al, bh0, bh1);
            mma_bf16(acc[2 * nt2 + 1], al, bh2, bh3);
        }
    }

    // Epilogue: c0,c1 -> (row0, 2tig..+1), c2,c3 -> (row1, 2tig..+1)
    if (row0 < M) {
        float* p = C + (size_t)row0 * NT + tig * 2;
        #pragma unroll
        for (int t = 0; t < NTILE; ++t)
            *(float2*)(p + t * 8) = make_float2(acc[t][0], acc[t][1]);
    }
    if (row1 < M) {
        float* p = C + (size_t)row1 * NT + tig * 2;
        #pragma unroll
        for (int t = 0; t < NTILE; ++t)
            *(float2*)(p + t * 8) = make_float2(acc[t][2], acc[t][3]);
    }
}

// ---------------------------------------------------------------------------
// Weight pre-transform: W[k][n] fp32 -> Wt_hi/Wt_lo[n][k] bf16 split
// ---------------------------------------------------------------------------
__global__ void convert_wt(const float* __restrict__ W,
                           __nv_bfloat16* __restrict__ hi,
                           __nv_bfloat16* __restrict__ lo, int Ncols)
{
    const int i = blockIdx.x * blockDim.x + threadIdx.x;
    if (i >= Ncols * 128) return;
    const int n = i >> 7;
    const int k = i & 127;
    const float v = W[(size_t)k * Ncols + n];
    const __nv_bfloat16 h = __float2bfloat16(v);
    hi[i] = h;
    lo[i] = __float2bfloat16(v - __bfloat162float(h));
}

// Feature split: fp32 -> bf16 hi/lo (vectorized x4)
__global__ void convert_x(const float* __restrict__ x,
                          __nv_bfloat16* __restrict__ hi,
                          __nv_bfloat16* __restrict__ lo, int n4)
{
    const int i = blockIdx.x * blockDim.x + threadIdx.x;
    if (i >= n4) return;
    const float4 v = ((const float4*)x)[i];
    float vv[4] = {v.x, v.y, v.z, v.w};
    __nv_bfloat16 h[4], l[4];
    #pragma unroll
    for (int j = 0; j < 4; ++j) {
        h[j] = __float2bfloat16(vv[j]);
        l[j] = __float2bfloat16(vv[j] - __bfloat162float(h[j]));
    }
    __nv_bfloat162 h01, h23, l01, l23;
    h01.x = h[0]; h01.y = h[1]; h23.x = h[2]; h23.y = h[3];
    l01.x = l[0]; l01.y = l[1]; l23.x = l[2]; l23.y = l[3];
    ((__nv_bfloat162*)hi)[2 * i]     = h01;
    ((__nv_bfloat162*)hi)[2 * i + 1] = h23;
    ((__nv_bfloat162*)lo)[2 * i]     = l01;
    ((__nv_bfloat162*)lo)[2 * i + 1] = l23;
}

// ---------------------------------------------------------------------------
// SpMM + LayerNorm (+ReLU). One warp per node; 2-edge unroll for MLP.
// HILO: emit bf16 hi/lo split (feeds next GEMM). Else fp32 out.
// ---------------------------------------------------------------------------
template<int D, bool RELU, bool HILO>
__global__ void __launch_bounds__(256)
spmm_ln(const float* __restrict__ xw,
        const int* __restrict__ rowptr, const int* __restrict__ cols,
        float* __restrict__ out_f32,
        __nv_bfloat16* __restrict__ out_hi, __nv_bfloat16* __restrict__ out_lo,
        int Nn)
{
    const int node = blockIdx.x * (blockDim.x >> 5) + (threadIdx.x >> 5);
    if (node >= Nn) return;
    const int lane = threadIdx.x & 31;
    constexpr int V = D / 32;

    float acc0[V], acc1[V];
    #pragma unroll
    for (int v = 0; v < V; ++v) { acc0[v] = 0.f; acc1[v] = 0.f; }

    const int s = __ldg(&rowptr[node]);
    const int e = __ldg(&rowptr[node + 1]);

    int i = s;
    for (; i + 2 <= e; i += 2) {
        const int c0 = __ldg(&cols[i]);
        const int c1 = __ldg(&cols[i + 1]);
        if (V == 4) {
            float4 a = *(const float4*)(xw + (size_t)c0 * D + lane * 4);
            float4 b = *(const float4*)(xw + (size_t)c1 * D + lane * 4);
            acc0[0] += a.x; acc0[1] += a.y; acc0[2] += a.z; acc0[3] += a.w;
            acc1[0] += b.x; acc1[1] += b.y; acc1[2] += b.z; acc1[3] += b.w;
        } else {
            float2 a = *(const float2*)(xw + (size_t)c0 * D + lane * 2);
            float2 b = *(const float2*)(xw + (size_t)c1 * D + lane * 2);
            acc0[0] += a.x; acc0[1] += a.y;
            acc1[0] += b.x; acc1[1] += b.y;
        }
    }
    if (i < e) {
        const int c0 = __ldg(&cols[i]);
        if (V == 4) {
            float4 a = *(const float4*)(xw + (size_t)c0 * D + lane * 4);
            acc0[0] += a.x; acc0[1] += a.y; acc0[2] += a.z; acc0[3] += a.w;
        } else {
            float2 a = *(const float2*)(xw + (size_t)c0 * D + lane * 2);
            acc0[0] += a.x; acc0[1] += a.y;
        }
    }
    #pragma unroll
    for (int v = 0; v < V; ++v) acc0[v] += acc1[v];

    // LayerNorm across the warp
    float sum = 0.f, sumsq = 0.f;
    #pragma unroll
    for (int v = 0; v < V; ++v) { sum += acc0[v]; sumsq += acc0[v] * acc0[v]; }
    #pragma unroll
    for (int off = 16; off > 0; off >>= 1) {
        sum   += __shfl_xor_sync(0xFFFFFFFFu, sum,   off);
        sumsq += __shfl_xor_sync(0xFFFFFFFFu, sumsq, off);
    }
    const float inv_d = 1.f / (float)D;
    const float mean = sum * inv_d;
    float var = sumsq * inv_d - mean * mean;
    if (var < 0.f) var = 0.f;
    const float rstd = rsqrtf(var + LN_EPS);

    float y[V];
    #pragma unroll
    for (int v = 0; v < V; ++v) {
        float t = (acc0[v] - mean) * rstd;
        if (RELU) t = fmaxf(t, 0.f);
        y[v] = t;
    }

    const size_t base = (size_t)node * D + lane * V;
    if (HILO) {
        __nv_bfloat16 h[V], l[V];
        #pragma unroll
        for (int v = 0; v < V; ++v) {
            h[v] = __float2bfloat16(y[v]);
            l[v] = __float2bfloat16(y[v] - __bfloat162float(h[v]));
        }
        #pragma unroll
        for (int v = 0; v < V; v += 2) {
            __nv_bfloat162 ph, pl;
            ph.x = h[v]; ph.y = h[v + 1];
            pl.x = l[v]; pl.y = l[v + 1];
            *(__nv_bfloat162*)(out_hi + base + v) = ph;
            *(__nv_bfloat162*)(out_lo + base + v) = pl;
        }
    } else {
        if (V == 4) *(float4*)(out_f32 + base) = make_float4(y[0], y[1], y[2], y[3]);
        else        *(float2*)(out_f32 + base) = make_float2(y[0], y[1]);
    }
}

// ---------------------------------------------------------------------------
// Launch
// ---------------------------------------------------------------------------
extern "C" void kernel_launch(void* const* d_in, const int* in_sizes, int n_in,
                              void* d_out, int out_size)
{
    const float* feat = nullptr;
    const float* W0 = nullptr, *W1 = nullptr, *W2 = nullptr;
    const int* rowptr = nullptr;
    const int* elist  = nullptr;

    for (int i = 0; i < n_in; ++i) {
        const int sz = in_sizes[i];
        if (sz == N_NODES * D_IN)      feat = (const float*)d_in[i];
        else if (sz == D_IN * D_H) {
            if (!W0) W0 = (const float*)d_in[i];
            else     W1 = (const float*)d_in[i];
        }
        else if (sz == D_H * D_OUT)    W2 = (const float*)d_in[i];
        else if (sz == N_NODES + 1)    rowptr = (const int*)d_in[i];
        else if (sz == N_EDGES) {
            if (!elist) elist = (const int*)d_in[i];   // second one = edge_rows
        }
    }

    float* xw = nullptr;
    __nv_bfloat16 *hhi = nullptr, *hlo = nullptr, *whi = nullptr, *wlo = nullptr;
    cudaGetSymbolAddress((void**)&xw,  g_xw);
    cudaGetSymbolAddress((void**)&hhi, g_h_hi);
    cudaGetSymbolAddress((void**)&hlo, g_h_lo);
    cudaGetSymbolAddress((void**)&whi, g_w_hi);
    cudaGetSymbolAddress((void**)&wlo, g_w_lo);
    __nv_bfloat16* w0hi = whi;                 __nv_bfloat16* w0lo = wlo;
    __nv_bfloat16* w1hi = whi + 128 * 128;     __nv_bfloat16* w1lo = wlo + 128 * 128;
    __nv_bfloat16* w2hi = whi + 2 * 128 * 128; __nv_bfloat16* w2lo = wlo + 2 * 128 * 128;

    // Dynamic smem for B staging: 2 * NT * 136 bf16
    const int smem128 = 2 * 128 * 136 * 2;  // 69632
    const int smem64  = 2 * 64  * 136 * 2;  // 34816
    cudaFuncSetAttribute(gemm_mma<128>,
                         cudaFuncAttributeMaxDynamicSharedMemorySize, smem128);
    cudaFuncSetAttribute(gemm_mma<64>,
                         cudaFuncAttributeMaxDynamicSharedMemorySize, smem64);

    const int gemm_grid = (N_NODES + 127) / 128;   // 391
    const int spmm_grid = (N_NODES + 7) / 8;       // 8 nodes/block

    // Prep: weight transpose+split, feature split
    convert_wt<<<(128 * 128 + 255) / 256, 256>>>(W0, w0hi, w0lo, 128);
    convert_wt<<<(128 * 128 + 255) / 256, 256>>>(W1, w1hi, w1lo, 128);
    convert_wt<<<(64  * 128 + 255) / 256, 256>>>(W2, w2hi, w2lo, 64);
    convert_x<<<(N_NODES * D_IN / 4 + 255) / 256, 256>>>(feat, hhi, hlo,
                                                         N_NODES * D_IN / 4);

    // Layer 0
    gemm_mma<128><<<gemm_grid, 256, smem128>>>(hhi, hlo, w0hi, w0lo, xw, N_NODES);
    spmm_ln<128, true, true><<<spmm_grid, 256>>>(xw, rowptr, elist,
                                                 nullptr, hhi, hlo, N_NODES);
    // Layer 1
    gemm_mma<128><<<gemm_grid, 256, smem128>>>(hhi, hlo, w1hi, w1lo, xw, N_NODES);
    spmm_ln<128, true, true><<<spmm_grid, 256>>>(xw, rowptr, elist,
                                                 nullptr, hhi, hlo, N_NODES);
    // Layer 2
    gemm_mma<64><<<gemm_grid, 256, smem64>>>(hhi, hlo, w2hi, w2lo, xw, N_NODES);
    spmm_ln<64, false, false><<<spmm_grid, 256>>>(xw, rowptr, elist,
                                                  (float*)d_out, nullptr, nullptr,
                                                  N_NODES);
}

// round 7
// speedup vs baseline: 1.8837x; 1.8837x over previous
#include <cuda_runtime.h>
#include <cuda_fp16.h>
#include <cuda_bf16.h>
#include <cstdint>

// ---------------------------------------------------------------------------
// Problem constants
// ---------------------------------------------------------------------------
#define N_NODES 50000
#define D_IN    128
#define D_H     128
#define D_OUT   64
#define N_EDGES 800000
#define LN_EPS  1e-5f

// ---------------------------------------------------------------------------
// Scratch (__device__ globals: allocation-free rule)
// ---------------------------------------------------------------------------
__device__ float  g_xw[N_NODES * D_H];      // GEMM out / SpMM in (fp32)
__device__ float  g_h [N_NODES * D_H];      // post-LN hidden state (fp32)
__device__ __half g_wt[3][128 * 128];       // weights transposed [n][k], fp16

// ---------------------------------------------------------------------------
// PTX helpers (sm_80-era: ldmatrix + mma.sync, no arch-suffix gating)
// ---------------------------------------------------------------------------
__device__ __forceinline__ uint32_t smem_to_u32(const void* p) {
    uint32_t a;
    asm("{ .reg .u64 t; cvta.to.shared.u64 t, %1; cvt.u32.u64 %0, t; }"
        : "=r"(a) : "l"(p));
    return a;
}

// Pack two fp32 -> one fp16x2 register (lo = x, hi = y).
// cvt.rn.f16x2.f32 d, a, b packs a into the UPPER half, b into the LOWER.
__device__ __forceinline__ uint32_t pack_f16x2(float lo, float hi) {
    uint32_t r;
    asm("cvt.rn.f16x2.f32 %0, %1, %2;" : "=r"(r) : "f"(hi), "f"(lo));
    return r;
}

__device__ __forceinline__ void ldm_x4(uint32_t& r0, uint32_t& r1,
                                       uint32_t& r2, uint32_t& r3,
                                       uint32_t addr) {
    asm volatile("ldmatrix.sync.aligned.m8n8.x4.shared.b16 {%0,%1,%2,%3}, [%4];"
                 : "=r"(r0), "=r"(r1), "=r"(r2), "=r"(r3) : "r"(addr));
}

__device__ __forceinline__ void mma_f16(float* d, const uint32_t* a,
                                        uint32_t b0, uint32_t b1) {
    asm volatile(
        "mma.sync.aligned.m16n8k16.row.col.f32.f16.f16.f32 "
        "{%0,%1,%2,%3}, {%4,%5,%6,%7}, {%8,%9}, {%0,%1,%2,%3};"
        : "+f"(d[0]), "+f"(d[1]), "+f"(d[2]), "+f"(d[3])
        : "r"(a[0]), "r"(a[1]), "r"(a[2]), "r"(a[3]), "r"(b0), "r"(b1));
}

// ---------------------------------------------------------------------------
// GEMM: C[M, NT] = A[M,128] @ B^T.  A fp32 (converted to fp16 in-register),
// B fp16 transposed [n][k].  fp32 accumulate in HMMA.
// CTA: 256 threads = 8 warps; warp w owns rows [blk*128 + w*16, +16) x NT.
// B staged in smem, rows padded to 136 halves (272B) for conflict-free
// ldmatrix.  A fragments loaded straight from global (coalesced float2:
// lanes 4q..4q+3 cover one row's 32B chunk).
// ---------------------------------------------------------------------------
template<int NT>
__global__ void __launch_bounds__(256)
gemm_f16(const float* __restrict__ A, const __half* __restrict__ Bt,
         float* __restrict__ C, int M)
{
    extern __shared__ __half smB[];   // [NT][136]

    // Stage B (NT rows x 128 halves = 16 x 16B chunks per row)
    for (int i = threadIdx.x; i < NT * 16; i += 256) {
        const int n = i >> 4, c = i & 15;
        ((uint4*)(smB + n * 136))[c] = ((const uint4*)(Bt + (size_t)n * 128))[c];
    }
    __syncthreads();

    const int lane = threadIdx.x & 31;
    const int wid  = threadIdx.x >> 5;
    const int g    = lane >> 2;        // octet row within 8
    const int tig  = lane & 3;         // thread-in-group -> k pair
    const int R    = blockIdx.x * 128 + wid * 16;
    const int row0 = R + g;
    const int row1 = R + g + 8;
    const int cr0  = row0 < M ? row0 : M - 1;   // clamp; OOB values unused
    const int cr1  = row1 < M ? row1 : M - 1;

    // ldmatrix lane address: quad q -> (n-half, k-half) of a 16x16 B tile
    const int q  = lane >> 3;
    const int rr = lane & 7;
    const uint32_t lane_off =
        (uint32_t)((((q & 2) ? 8 : 0) + rr) * 272 + ((q & 1) ? 16 : 0));
    const uint32_t sB = smem_to_u32(smB) + lane_off;

    constexpr int NTILE = NT / 8;
    float acc[NTILE][4];
    #pragma unroll
    for (int t = 0; t < NTILE; ++t)
        #pragma unroll
        for (int j = 0; j < 4; ++j) acc[t][j] = 0.f;

    const float* A0 = A + (size_t)cr0 * 128 + tig * 2;
    const float* A1 = A + (size_t)cr1 * 128 + tig * 2;

    #pragma unroll
    for (int k0 = 0; k0 < 128; k0 += 16) {
        // A fragments: a0:(g,k) a1:(g+8,k) a2:(g,k+8) a3:(g+8,k+8)
        float2 f0 = *(const float2*)(A0 + k0);
        float2 f1 = *(const float2*)(A1 + k0);
        float2 f2 = *(const float2*)(A0 + k0 + 8);
        float2 f3 = *(const float2*)(A1 + k0 + 8);
        uint32_t a[4];
        a[0] = pack_f16x2(f0.x, f0.y);
        a[1] = pack_f16x2(f1.x, f1.y);
        a[2] = pack_f16x2(f2.x, f2.y);
        a[3] = pack_f16x2(f3.x, f3.y);

        #pragma unroll
        for (int nt2 = 0; nt2 < NT / 16; ++nt2) {
            const uint32_t off = (uint32_t)(nt2 * 16 * 272 + k0 * 2);
            uint32_t b0, b1, b2, b3;
            ldm_x4(b0, b1, b2, b3, sB + off);
            mma_f16(acc[2 * nt2],     a, b0, b1);
            mma_f16(acc[2 * nt2 + 1], a, b2, b3);
        }
    }

    // Epilogue: c0,c1 -> (row0, 2tig..+1), c2,c3 -> (row1, 2tig..+1)
    if (row0 < M) {
        float* p = C + (size_t)row0 * NT + tig * 2;
        #pragma unroll
        for (int t = 0; t < NTILE; ++t)
            *(float2*)(p + t * 8) = make_float2(acc[t][0], acc[t][1]);
    }
    if (row1 < M) {
        float* p = C + (size_t)row1 * NT + tig * 2;
        #pragma unroll
        for (int t = 0; t < NTILE; ++t)
            *(float2*)(p + t * 8) = make_float2(acc[t][2], acc[t][3]);
    }
}

// ---------------------------------------------------------------------------
// Weight pre-transform: W[k][n] fp32 -> Wt[n][k] fp16 (all 3 weights, 1 kernel)
// segment 0: W0 (128x128), 1: W1 (128x128), 2: W2 (128x64)
// ---------------------------------------------------------------------------
__global__ void convert_wt_all(const float* __restrict__ W0,
                               const float* __restrict__ W1,
                               const float* __restrict__ W2,
                               __half* __restrict__ wt)   // g_wt base
{
    const int i = blockIdx.x * blockDim.x + threadIdx.x;
    const int total01 = 128 * 128;
    if (i < total01) {                       // W0
        const int n = i >> 7, k = i & 127;
        wt[i] = __float2half(W0[(size_t)k * 128 + n]);
    } else if (i < 2 * total01) {            // W1
        const int j = i - total01;
        const int n = j >> 7, k = j & 127;
        wt[total01 + j] = __float2half(W1[(size_t)k * 128 + n]);
    } else if (i < 2 * total01 + 64 * 128) { // W2
        const int j = i - 2 * total01;
        const int n = j >> 7, k = j & 127;
        wt[2 * total01 + j] = __float2half(W2[(size_t)k * 64 + n]);
    }
}

// ---------------------------------------------------------------------------
// SpMM + LayerNorm (+ReLU): one warp per node, 2-edge unroll, fp32 in/out.
// ---------------------------------------------------------------------------
template<int D, bool RELU>
__global__ void __launch_bounds__(256)
spmm_ln(const float* __restrict__ xw,
        const int* __restrict__ rowptr, const int* __restrict__ cols,
        float* __restrict__ out, int Nn)
{
    const int node = blockIdx.x * (blockDim.x >> 5) + (threadIdx.x >> 5);
    if (node >= Nn) return;
    const int lane = threadIdx.x & 31;
    constexpr int V = D / 32;

    float acc0[V], acc1[V];
    #pragma unroll
    for (int v = 0; v < V; ++v) { acc0[v] = 0.f; acc1[v] = 0.f; }

    const int s = __ldg(&rowptr[node]);
    const int e = __ldg(&rowptr[node + 1]);

    int i = s;
    for (; i + 2 <= e; i += 2) {
        const int c0 = __ldg(&cols[i]);
        const int c1 = __ldg(&cols[i + 1]);
        if (V == 4) {
            float4 a = *(const float4*)(xw + (size_t)c0 * D + lane * 4);
            float4 b = *(const float4*)(xw + (size_t)c1 * D + lane * 4);
            acc0[0] += a.x; acc0[1] += a.y; acc0[2] += a.z; acc0[3] += a.w;
            acc1[0] += b.x; acc1[1] += b.y; acc1[2] += b.z; acc1[3] += b.w;
        } else {
            float2 a = *(const float2*)(xw + (size_t)c0 * D + lane * 2);
            float2 b = *(const float2*)(xw + (size_t)c1 * D + lane * 2);
            acc0[0] += a.x; acc0[1] += a.y;
            acc1[0] += b.x; acc1[1] += b.y;
        }
    }
    if (i < e) {
        const int c0 = __ldg(&cols[i]);
        if (V == 4) {
            float4 a = *(const float4*)(xw + (size_t)c0 * D + lane * 4);
            acc0[0] += a.x; acc0[1] += a.y; acc0[2] += a.z; acc0[3] += a.w;
        } else {
            float2 a = *(const float2*)(xw + (size_t)c0 * D + lane * 2);
            acc0[0] += a.x; acc0[1] += a.y;
        }
    }
    #pragma unroll
    for (int v = 0; v < V; ++v) acc0[v] += acc1[v];

    // LayerNorm across the warp
    float sum = 0.f, sumsq = 0.f;
    #pragma unroll
    for (int v = 0; v < V; ++v) { sum += acc0[v]; sumsq += acc0[v] * acc0[v]; }
    #pragma unroll
    for (int off = 16; off > 0; off >>= 1) {
        sum   += __shfl_xor_sync(0xFFFFFFFFu, sum,   off);
        sumsq += __shfl_xor_sync(0xFFFFFFFFu, sumsq, off);
    }
    const float inv_d = 1.f / (float)D;
    const float mean = sum * inv_d;
    float var = sumsq * inv_d - mean * mean;
    if (var < 0.f) var = 0.f;
    const float rstd = rsqrtf(var + LN_EPS);

    float y[V];
    #pragma unroll
    for (int v = 0; v < V; ++v) {
        float t = (acc0[v] - mean) * rstd;
        if (RELU) t = fmaxf(t, 0.f);
        y[v] = t;
    }

    float* dst = out + (size_t)node * D + lane * V;
    if (V == 4) *(float4*)dst = make_float4(y[0], y[1], y[2], y[3]);
    else        *(float2*)dst = make_float2(y[0], y[1]);
}

// ---------------------------------------------------------------------------
// Launch
// ---------------------------------------------------------------------------
extern "C" void kernel_launch(void* const* d_in, const int* in_sizes, int n_in,
                              void* d_out, int out_size)
{
    const float* feat = nullptr;
    const float* W0 = nullptr, *W1 = nullptr, *W2 = nullptr;
    const int* rowptr = nullptr;
    const int* elist  = nullptr;

    for (int i = 0; i < n_in; ++i) {
        const int sz = in_sizes[i];
        if (sz == N_NODES * D_IN)      feat = (const float*)d_in[i];
        else if (sz == D_IN * D_H) {
            if (!W0) W0 = (const float*)d_in[i];
            else     W1 = (const float*)d_in[i];
        }
        else if (sz == D_H * D_OUT)    W2 = (const float*)d_in[i];
        else if (sz == N_NODES + 1)    rowptr = (const int*)d_in[i];
        else if (sz == N_EDGES) {
            if (!elist) elist = (const int*)d_in[i];  // second one = edge_rows
        }
    }

    float* xw = nullptr;
    float* h  = nullptr;
    __half* wt = nullptr;
    cudaGetSymbolAddress((void**)&xw, g_xw);
    cudaGetSymbolAddress((void**)&h,  g_h);
    cudaGetSymbolAddress((void**)&wt, g_wt);
    __half* w0t = wt;
    __half* w1t = wt + 128 * 128;
    __half* w2t = wt + 2 * 128 * 128;

    const int smem128 = 128 * 136 * 2;   // 34816 B
    const int smem64  = 64  * 136 * 2;   // 17408 B
    cudaFuncSetAttribute(gemm_f16<128>,
                         cudaFuncAttributeMaxDynamicSharedMemorySize, smem128);
    cudaFuncSetAttribute(gemm_f16<64>,
                         cudaFuncAttributeMaxDynamicSharedMemorySize, smem64);

    const int gemm_grid = (N_NODES + 127) / 128;   // 391
    const int spmm_grid = (N_NODES + 7) / 8;       // 8 nodes/block

    // Weight transpose + fp16 convert (one kernel, 3 segments)
    const int wt_total = 2 * 128 * 128 + 64 * 128;
    convert_wt_all<<<(wt_total + 255) / 256, 256>>>(W0, W1, W2, wt);

    // Layer 0: feat @ W0 -> xw; SpMM+LN+ReLU -> h
    gemm_f16<128><<<gemm_grid, 256, smem128>>>(feat, w0t, xw, N_NODES);
    spmm_ln<128, true><<<spmm_grid, 256>>>(xw, rowptr, elist, h, N_NODES);

    // Layer 1: h @ W1 -> xw; SpMM+LN+ReLU -> h
    gemm_f16<128><<<gemm_grid, 256, smem128>>>(h, w1t, xw, N_NODES);
    spmm_ln<128, true><<<spmm_grid, 256>>>(xw, rowptr, elist, h, N_NODES);

    // Layer 2: h @ W2 -> xw; SpMM+LN (no ReLU) -> d_out
    gemm_f16<64><<<gemm_grid, 256, smem64>>>(h, w2t, xw, N_NODES);
    spmm_ln<64, false><<<spmm_grid, 256>>>(xw, rowptr, elist,
                                           (float*)d_out, N_NODES);
}

// round 12
// speedup vs baseline: 2.0697x; 1.0987x over previous
#include <cuda_runtime.h>
#include <cuda_fp16.h>
#include <cstdint>

// ---------------------------------------------------------------------------
// Problem constants
// ---------------------------------------------------------------------------
#define N_NODES 50000
#define D_IN    128
#define D_H     128
#define D_OUT   64
#define N_EDGES 800000
#define LN_EPS  1e-5f

// ---------------------------------------------------------------------------
// Scratch (__device__ globals: allocation-free rule)
// ---------------------------------------------------------------------------
__device__ __half g_xw[N_NODES * D_H];      // GEMM out / SpMM in (fp16)
__device__ float  g_h [N_NODES * D_H];      // post-LN hidden state (fp32)
__device__ __half g_wt[3][128 * 128];       // weights transposed [n][k], fp16

// ---------------------------------------------------------------------------
// PTX helpers (sm_80-era: ldmatrix + mma.sync, no arch-suffix gating)
// ---------------------------------------------------------------------------
__device__ __forceinline__ uint32_t smem_to_u32(const void* p) {
    uint32_t a;
    asm("{ .reg .u64 t; cvta.to.shared.u64 t, %1; cvt.u32.u64 %0, t; }"
        : "=r"(a) : "l"(p));
    return a;
}

// Pack two fp32 -> one fp16x2 register (lo = first arg, hi = second).
// cvt.rn.f16x2.f32 d, a, b puts a in UPPER half, b in LOWER.
__device__ __forceinline__ uint32_t pack_f16x2(float lo, float hi) {
    uint32_t r;
    asm("cvt.rn.f16x2.f32 %0, %1, %2;" : "=r"(r) : "f"(hi), "f"(lo));
    return r;
}

__device__ __forceinline__ void ldm_x4(uint32_t& r0, uint32_t& r1,
                                       uint32_t& r2, uint32_t& r3,
                                       uint32_t addr) {
    asm volatile("ldmatrix.sync.aligned.m8n8.x4.shared.b16 {%0,%1,%2,%3}, [%4];"
                 : "=r"(r0), "=r"(r1), "=r"(r2), "=r"(r3) : "r"(addr));
}

__device__ __forceinline__ void mma_f16(float* d, const uint32_t* a,
                                        uint32_t b0, uint32_t b1) {
    asm volatile(
        "mma.sync.aligned.m16n8k16.row.col.f32.f16.f16.f32 "
        "{%0,%1,%2,%3}, {%4,%5,%6,%7}, {%8,%9}, {%0,%1,%2,%3};"
        : "+f"(d[0]), "+f"(d[1]), "+f"(d[2]), "+f"(d[3])
        : "r"(a[0]), "r"(a[1]), "r"(a[2]), "r"(a[3]), "r"(b0), "r"(b1));
}

// ---------------------------------------------------------------------------
// GEMM: C[M, NT](fp16) = A[M,128](fp32) @ B^T(fp16 [n][k]).
// A staged in smem as fp16 (bulk coalesced load + convert); B staged in smem.
// Mainloop = pure ldmatrix + mma. Rows padded to 136 halves (272B) =>
// conflict-free ldmatrix (272 mod 128 = 16: 8 rows hit distinct quads).
//
// ldmatrix.x4 fragment map: register r_i <- matrix i, matrix i's rows come
// from lane octet i's addresses.
//   A operand needs a1=(row+8,k+0), a2=(row,k+8):  octet map q&1->row+8, q&2->k+16B
//   B operand needs b-pairs (n,k0),(n,k8) then (n+8,*): octet map q&1->k+16B, q&2->n+8
// (R8 bug: B's map was reused for A, swapping a1/a2.)
// ---------------------------------------------------------------------------
template<int NT>
__global__ void __launch_bounds__(256)
gemm_f16(const float* __restrict__ A, const __half* __restrict__ Bt,
         __half* __restrict__ C, int M)
{
    extern __shared__ __half sm[];
    __half* smA = sm;               // [128][136]
    __half* smB = sm + 128 * 136;   // [NT][136]

    const int tid = threadIdx.x;
    const int m0  = blockIdx.x * 128;

    // Stage B (NT rows x 128 halves = 16 x 16B chunks per row)
    for (int i = tid; i < NT * 16; i += 256) {
        const int n = i >> 4, c = i & 15;
        ((uint4*)(smB + n * 136))[c] = ((const uint4*)(Bt + (size_t)n * 128))[c];
    }

    // Stage A: 128 rows x 128 fp32 -> fp16 (uint2 = 4 halves per step)
    for (int i = tid; i < 128 * 32; i += 256) {
        const int r  = i >> 5;
        const int c4 = i & 31;
        float4 v = make_float4(0.f, 0.f, 0.f, 0.f);
        if (m0 + r < M)
            v = ((const float4*)(A + (size_t)(m0 + r) * 128))[c4];
        uint2 p;
        p.x = pack_f16x2(v.x, v.y);
        p.y = pack_f16x2(v.z, v.w);
        *(uint2*)(smA + r * 136 + c4 * 4) = p;
    }
    __syncthreads();

    const int lane = tid & 31;
    const int wid  = tid >> 5;
    const int g    = lane >> 2;        // octet row
    const int tig  = lane & 3;         // thread-in-group -> col pair
    const int row0 = m0 + wid * 16 + g;
    const int row1 = row0 + 8;

    const int q  = lane >> 3;
    const int rr = lane & 7;
    // A map: q&1 -> +8 rows, q&2 -> +16B in k
    const uint32_t laneA =
        (uint32_t)((((q & 1) ? 8 : 0) + rr) * 272 + ((q & 2) ? 16 : 0));
    // B map: q&1 -> +16B in k, q&2 -> +8 n-rows
    const uint32_t laneB =
        (uint32_t)((((q & 2) ? 8 : 0) + rr) * 272 + ((q & 1) ? 16 : 0));
    const uint32_t sA = smem_to_u32(smA) + laneA + (uint32_t)(wid * 16 * 272);
    const uint32_t sB = smem_to_u32(smB) + laneB;

    constexpr int NTILE = NT / 8;
    float acc[NTILE][4];
    #pragma unroll
    for (int t = 0; t < NTILE; ++t)
        #pragma unroll
        for (int j = 0; j < 4; ++j) acc[t][j] = 0.f;

    #pragma unroll
    for (int k0 = 0; k0 < 128; k0 += 16) {
        uint32_t a[4];
        ldm_x4(a[0], a[1], a[2], a[3], sA + (uint32_t)(k0 * 2));

        #pragma unroll
        for (int nt2 = 0; nt2 < NT / 16; ++nt2) {
            const uint32_t off = (uint32_t)(nt2 * 16 * 272 + k0 * 2);
            uint32_t b0, b1, b2, b3;
            ldm_x4(b0, b1, b2, b3, sB + off);
            mma_f16(acc[2 * nt2],     a, b0, b1);
            mma_f16(acc[2 * nt2 + 1], a, b2, b3);
        }
    }

    // Epilogue (fp16 out): c0,c1 -> (row0, 2tig..+1); c2,c3 -> (row1, ...)
    if (row0 < M) {
        __half* p = C + (size_t)row0 * NT + tig * 2;
        #pragma unroll
        for (int t = 0; t < NTILE; ++t)
            *(uint32_t*)(p + t * 8) = pack_f16x2(acc[t][0], acc[t][1]);
    }
    if (row1 < M) {
        __half* p = C + (size_t)row1 * NT + tig * 2;
        #pragma unroll
        for (int t = 0; t < NTILE; ++t)
            *(uint32_t*)(p + t * 8) = pack_f16x2(acc[t][2], acc[t][3]);
    }
}

// ---------------------------------------------------------------------------
// Weight pre-transform: W[k][n] fp32 -> Wt[n][k] fp16 (all 3 weights)
// ---------------------------------------------------------------------------
__global__ void convert_wt_all(const float* __restrict__ W0,
                               const float* __restrict__ W1,
                               const float* __restrict__ W2,
                               __half* __restrict__ wt)
{
    const int i = blockIdx.x * blockDim.x + threadIdx.x;
    const int total01 = 128 * 128;
    if (i < total01) {                       // W0
        const int n = i >> 7, k = i & 127;
        wt[i] = __float2half(W0[(size_t)k * 128 + n]);
    } else if (i < 2 * total01) {            // W1
        const int j = i - total01;
        const int n = j >> 7, k = j & 127;
        wt[total01 + j] = __float2half(W1[(size_t)k * 128 + n]);
    } else if (i < 2 * total01 + 64 * 128) { // W2
        const int j = i - 2 * total01;
        const int n = j >> 7, k = j & 127;
        wt[2 * total01 + j] = __float2half(W2[(size_t)k * 64 + n]);
    }
}

// ---------------------------------------------------------------------------
// SpMM + LayerNorm (+ReLU): one warp per node, 2-edge unroll.
// xw is fp16 (half the L2 gather traffic); accumulate fp32.
// ---------------------------------------------------------------------------
template<int D, bool RELU>
__global__ void __launch_bounds__(256)
spmm_ln(const __half* __restrict__ xw,
        const int* __restrict__ rowptr, const int* __restrict__ cols,
        float* __restrict__ out, int Nn)
{
    const int node = blockIdx.x * (blockDim.x >> 5) + (threadIdx.x >> 5);
    if (node >= Nn) return;
    const int lane = threadIdx.x & 31;
    constexpr int V = D / 32;   // 4 (D=128) or 2 (D=64)

    float acc0[V], acc1[V];
    #pragma unroll
    for (int v = 0; v < V; ++v) { acc0[v] = 0.f; acc1[v] = 0.f; }

    const int s = __ldg(&rowptr[node]);
    const int e = __ldg(&rowptr[node + 1]);

    int i = s;
    for (; i + 2 <= e; i += 2) {
        const int c0 = __ldg(&cols[i]);
        const int c1 = __ldg(&cols[i + 1]);
        if (V == 4) {
            uint2 ua = *(const uint2*)(xw + (size_t)c0 * D + lane * 4);
            uint2 ub = *(const uint2*)(xw + (size_t)c1 * D + lane * 4);
            float2 a0 = __half22float2(*(__half2*)&ua.x);
            float2 a1 = __half22float2(*(__half2*)&ua.y);
            float2 b0 = __half22float2(*(__half2*)&ub.x);
            float2 b1 = __half22float2(*(__half2*)&ub.y);
            acc0[0] += a0.x; acc0[1] += a0.y; acc0[2] += a1.x; acc0[3] += a1.y;
            acc1[0] += b0.x; acc1[1] += b0.y; acc1[2] += b1.x; acc1[3] += b1.y;
        } else {
            uint32_t ua = *(const uint32_t*)(xw + (size_t)c0 * D + lane * 2);
            uint32_t ub = *(const uint32_t*)(xw + (size_t)c1 * D + lane * 2);
            float2 a0 = __half22float2(*(__half2*)&ua);
            float2 b0 = __half22float2(*(__half2*)&ub);
            acc0[0] += a0.x; acc0[1] += a0.y;
            acc1[0] += b0.x; acc1[1] += b0.y;
        }
    }
    if (i < e) {
        const int c0 = __ldg(&cols[i]);
        if (V == 4) {
            uint2 ua = *(const uint2*)(xw + (size_t)c0 * D + lane * 4);
            float2 a0 = __half22float2(*(__half2*)&ua.x);
            float2 a1 = __half22float2(*(__half2*)&ua.y);
            acc0[0] += a0.x; acc0[1] += a0.y; acc0[2] += a1.x; acc0[3] += a1.y;
        } else {
            uint32_t ua = *(const uint32_t*)(xw + (size_t)c0 * D + lane * 2);
            float2 a0 = __half22float2(*(__half2*)&ua);
            acc0[0] += a0.x; acc0[1] += a0.y;
        }
    }
    #pragma unroll
    for (int v = 0; v < V; ++v) acc0[v] += acc1[v];

    // LayerNorm across the warp
    float sum = 0.f, sumsq = 0.f;
    #pragma unroll
    for (int v = 0; v < V; ++v) { sum += acc0[v]; sumsq += acc0[v] * acc0[v]; }
    #pragma unroll
    for (int off = 16; off > 0; off >>= 1) {
        sum   += __shfl_xor_sync(0xFFFFFFFFu, sum,   off);
        sumsq += __shfl_xor_sync(0xFFFFFFFFu, sumsq, off);
    }
    const float inv_d = 1.f / (float)D;
    const float mean = sum * inv_d;
    float var = sumsq * inv_d - mean * mean;
    if (var < 0.f) var = 0.f;
    const float rstd = rsqrtf(var + LN_EPS);

    float y[V];
    #pragma unroll
    for (int v = 0; v < V; ++v) {
        float t = (acc0[v] - mean) * rstd;
        if (RELU) t = fmaxf(t, 0.f);
        y[v] = t;
    }

    float* dst = out + (size_t)node * D + lane * V;
    if (V == 4) *(float4*)dst = make_float4(y[0], y[1], y[2], y[3]);
    else        *(float2*)dst = make_float2(y[0], y[1]);
}

// ---------------------------------------------------------------------------
// Launch
// ---------------------------------------------------------------------------
extern "C" void kernel_launch(void* const* d_in, const int* in_sizes, int n_in,
                              void* d_out, int out_size)
{
    const float* feat = nullptr;
    const float* W0 = nullptr, *W1 = nullptr, *W2 = nullptr;
    const int* rowptr = nullptr;
    const int* elist  = nullptr;

    for (int i = 0; i < n_in; ++i) {
        const int sz = in_sizes[i];
        if (sz == N_NODES * D_IN)      feat = (const float*)d_in[i];
        else if (sz == D_IN * D_H) {
            if (!W0) W0 = (const float*)d_in[i];
            else     W1 = (const float*)d_in[i];
        }
        else if (sz == D_H * D_OUT)    W2 = (const float*)d_in[i];
        else if (sz == N_NODES + 1)    rowptr = (const int*)d_in[i];
        else if (sz == N_EDGES) {
            if (!elist) elist = (const int*)d_in[i];  // second one = edge_rows
        }
    }

    __half* xw = nullptr;
    float*  h  = nullptr;
    __half* wt = nullptr;
    cudaGetSymbolAddress((void**)&xw, g_xw);
    cudaGetSymbolAddress((void**)&h,  g_h);
    cudaGetSymbolAddress((void**)&wt, g_wt);
    __half* w0t = wt;
    __half* w1t = wt + 128 * 128;
    __half* w2t = wt + 2 * 128 * 128;

    const int smem128 = (128 + 128) * 136 * 2;   // 69632 B
    const int smem64  = (128 + 64)  * 136 * 2;   // 52224 B
    cudaFuncSetAttribute(gemm_f16<128>,
                         cudaFuncAttributeMaxDynamicSharedMemorySize, smem128);
    cudaFuncSetAttribute(gemm_f16<64>,
                         cudaFuncAttributeMaxDynamicSharedMemorySize, smem64);

    const int gemm_grid = (N_NODES + 127) / 128;   // 391
    const int spmm_grid = (N_NODES + 7) / 8;       // 8 nodes/block

    // Weight transpose + fp16 convert
    const int wt_total = 2 * 128 * 128 + 64 * 128;
    convert_wt_all<<<(wt_total + 255) / 256, 256>>>(W0, W1, W2, wt);

    // Layer 0: feat @ W0 -> xw; SpMM+LN+ReLU -> h
    gemm_f16<128><<<gemm_grid, 256, smem128>>>(feat, w0t, xw, N_NODES);
    spmm_ln<128, true><<<spmm_grid, 256>>>(xw, rowptr, elist, h, N_NODES);

    // Layer 1: h @ W1 -> xw; SpMM+LN+ReLU -> h
    gemm_f16<128><<<gemm_grid, 256, smem128>>>(h, w1t, xw, N_NODES);
    spmm_ln<128, true><<<spmm_grid, 256>>>(xw, rowptr, elist, h, N_NODES);

    // Layer 2: h @ W2 -> xw; SpMM+LN (no ReLU) -> d_out
    gemm_f16<64><<<gemm_grid, 256, smem64>>>(h, w2t, xw, N_NODES);
    spmm_ln<64, false><<<spmm_grid, 256>>>(xw, rowptr, elist,
                                           (float*)d_out, N_NODES);
}